// round 13
// baseline (speedup 1.0000x reference)
#include <cuda_runtime.h>
#include <cstdint>

// ---------------------------------------------------------------------------
// Single fused kernel, A entirely in registers.
//   prologue: t0 issues first TMA prefetch; every warp's lanes 0..9 compose
//             the 8 conv layers into the affine map columns in registers
//             (one augmented-matrix column per lane, no barriers), then all
//             lanes gather the full 9x10 A into private registers via shfl.
//   loop:     persistent triple-buffered TMA pipeline over 256-row tiles
//             (9216 B): prefetch next (wait_group.read 1 gate) -> mbarrier
//             wait -> in-place vector compute (pure register FMA for A) ->
//             async bulk store (no wait).
//   smem: 3*9216 + 24 = ~27.7 KB; regs ~143 -> 7 CTAs/SM.
// ---------------------------------------------------------------------------
#define TPB 64
#define RPT 4
#define ROWS_PER_TILE (TPB * RPT)            // 256
#define WORDS_PER_TILE (ROWS_PER_TILE * 9)   // 2304
#define BYTES_PER_TILE (WORDS_PER_TILE * 4)  // 9216
#define NBUF 3

__device__ __forceinline__ uint32_t smem_u32(const void* p) {
    uint32_t a;
    asm("{ .reg .u64 tmp; cvta.to.shared.u64 tmp, %1; cvt.u32.u64 %0, tmp; }"
        : "=r"(a) : "l"(p));
    return a;
}

__device__ __forceinline__ void mbar_wait(uint32_t mb, uint32_t parity) {
    uint32_t done;
    asm volatile(
        "{\n\t.reg .pred p;\n\t"
        "mbarrier.try_wait.parity.acquire.cta.shared::cta.b64 p, [%1], %2;\n\t"
        "selp.b32 %0, 1, 0, p;\n\t}"
        : "=r"(done) : "r"(mb), "r"(parity) : "memory");
    if (!done) {
        asm volatile(
            "{\n\t.reg .pred P1;\n\t"
            "WAIT_LOOP_%=:\n\t"
            "mbarrier.try_wait.parity.acquire.cta.shared::cta.b64 P1, [%0], %1, 0x989680;\n\t"
            "@P1 bra.uni WAIT_DONE_%=;\n\t"
            "bra.uni WAIT_LOOP_%=;\n\t"
            "WAIT_DONE_%=:\n\t}"
            :: "r"(mb), "r"(parity) : "memory");
    }
}

__global__ __launch_bounds__(TPB, 7)
void affine_kernel(const float* __restrict__ x,
                   const float* __restrict__ w,    // [8*9]
                   const float* __restrict__ bias, // [8]
                   float* __restrict__ out,
                   int nrows) {
    __shared__ __align__(128) float sx[NBUF][WORDS_PER_TILE];
    __shared__ __align__(8) unsigned long long mbar[NBUF];

    int t = threadIdx.x;
    int ntiles = (nrows + ROWS_PER_TILE - 1) / ROWS_PER_TILE;

    if (t == 0) {
#pragma unroll
        for (int i = 0; i < NBUF; i++)
            asm volatile("mbarrier.init.shared.b64 [%0], %1;"
                         :: "r"(smem_u32(&mbar[i])), "r"(1) : "memory");
    }
    __syncthreads();

    uint32_t s_mb[NBUF], s_bf[NBUF];
#pragma unroll
    for (int i = 0; i < NBUF; i++) {
        s_mb[i] = smem_u32(&mbar[i]);
        s_bf[i] = smem_u32(sx[i]);
    }

    // ---- prologue: prefetch my first tile (if full) into buffer 0 ----
    {
        long long tile0 = blockIdx.x;
        if (tile0 < ntiles && t == 0) {
            long long rows0 = (long long)nrows - tile0 * ROWS_PER_TILE;
            if (rows0 >= ROWS_PER_TILE) {
                const float* xg = x + tile0 * (long long)ROWS_PER_TILE * 9;
                asm volatile("mbarrier.arrive.expect_tx.shared.b64 _, [%0], %1;"
                             :: "r"(s_mb[0]), "r"((uint32_t)BYTES_PER_TILE) : "memory");
                asm volatile(
                    "cp.async.bulk.shared::cta.global.mbarrier::complete_tx::bytes "
                    "[%0], [%1], %2, [%3];"
                    :: "r"(s_bf[0]), "l"(xg), "r"((uint32_t)BYTES_PER_TILE), "r"(s_mb[0])
                    : "memory");
            }
        }
    }

    // ---- compose A per warp in registers (overlaps first TMA latency) ----
    // Lane l (clamped to column 9) owns one column of the augmented 9x10
    // matrix; columns evolve independently -> no communication until the
    // final shuffle gather.
    float ar[90];   // ar[o*10+c]: row o of A (c=0..8 weights, c=9 bias)
    {
        int lane = t & 31;
        int c = lane < 10 ? lane : 9;
        float col[9];
#pragma unroll
        for (int o = 0; o < 9; o++) col[o] = (o == c) ? 1.0f : 0.0f;

        for (int d = 0; d < 8; d++) {
            float wd[9];
#pragma unroll
            for (int z = 0; z < 9; z++) wd[z] = __ldg(&w[d * 9 + z]);

            float nc[9];
#pragma unroll
            for (int o = 0; o < 9; o++) {
                int i = o / 3, j = o % 3;
                float acc = 0.0f;
#pragma unroll
                for (int di = -1; di <= 1; di++) {
#pragma unroll
                    for (int dj = -1; dj <= 1; dj++) {
                        int ii = i + di, jj = j + dj;
                        if (ii >= 0 && ii < 3 && jj >= 0 && jj < 3)
                            acc += wd[(di + 1) * 3 + (dj + 1)] * col[ii * 3 + jj];
                    }
                }
                nc[o] = acc;
            }
            float bd = (c == 9) ? __ldg(&bias[d]) : 0.0f;
#pragma unroll
            for (int o = 0; o < 9; o++) col[o] = nc[o] + bd;
        }

        // gather the full A into every lane's registers
#pragma unroll
        for (int o = 0; o < 9; o++) {
#pragma unroll
            for (int cc = 0; cc < 10; cc++)
                ar[o * 10 + cc] = __shfl_sync(0xffffffffu, col[o], cc);
        }
    }

    uint32_t ph[NBUF] = {0u, 0u, 0u};
    int b = 0;
    for (long long tile = blockIdx.x; tile < ntiles; tile += gridDim.x) {
        int bn = (b + 1 == NBUF) ? 0 : b + 1;
        float* buf = sx[b];

        long long r0 = tile * ROWS_PER_TILE;
        int rows_here = (int)((((long long)nrows - r0) < ROWS_PER_TILE)
                                  ? (nrows - r0) : ROWS_PER_TILE);
        bool full = (rows_here == ROWS_PER_TILE);
        int cnt = rows_here * 9;
        const float* xg = x + r0 * 9;
        float*       og = out + r0 * 9;

        // ---- prefetch next tile into buffer bn ----
        long long ntile = tile + gridDim.x;
        if (ntile < ntiles && t == 0) {
            long long nrows_next = (long long)nrows - ntile * ROWS_PER_TILE;
            if (nrows_next >= ROWS_PER_TILE) {
                // buffer bn's store was issued 2 iterations ago; allow the
                // most recent store to stay outstanding
                asm volatile("cp.async.bulk.wait_group.read 1;" ::: "memory");
                const float* xgn = x + ntile * (long long)ROWS_PER_TILE * 9;
                asm volatile("mbarrier.arrive.expect_tx.shared.b64 _, [%0], %1;"
                             :: "r"(s_mb[bn]), "r"((uint32_t)BYTES_PER_TILE) : "memory");
                asm volatile(
                    "cp.async.bulk.shared::cta.global.mbarrier::complete_tx::bytes "
                    "[%0], [%1], %2, [%3];"
                    :: "r"(s_bf[bn]), "l"(xgn), "r"((uint32_t)BYTES_PER_TILE), "r"(s_mb[bn])
                    : "memory");
            }
        }

        if (full) {
            // ---- consume TMA-loaded tile ----
            mbar_wait(s_mb[b], ph[b]);
            ph[b] ^= 1;

            float* chunk = &buf[t * 36];   // this thread's 4 rows (144 B)
            float v[20];
            float y[18];

#pragma unroll
            for (int g = 0; g < 2; g++) {
                // group 0: rows 0,1 (words 0..17),  window = words 0..19
                // group 1: rows 2,3 (words 18..35), window = words 16..35
#pragma unroll
                for (int k = 0; k < 5; k++)
                    *(float4*)&v[4 * k] = *(const float4*)&chunk[16 * g + 4 * k];

                const float* xa = v + (g ? 2 : 0);
                const float* xb = xa + 9;

#pragma unroll
                for (int o = 0; o < 9; o++) {
                    float acc = ar[o * 10 + 9];
                    float acd = ar[o * 10 + 9];
#pragma unroll
                    for (int c = 0; c < 9; c++) {
                        acc = fmaf(ar[o * 10 + c], xa[c], acc);
                        acd = fmaf(ar[o * 10 + c], xb[c], acd);
                    }
                    y[o] = acc;
                    y[9 + o] = acd;
                }

                if (g == 0) {
                    *(float4*)&chunk[0]  = *(const float4*)&y[0];
                    *(float4*)&chunk[4]  = *(const float4*)&y[4];
                    *(float4*)&chunk[8]  = *(const float4*)&y[8];
                    *(float4*)&chunk[12] = *(const float4*)&y[12];
                    *(float2*)&chunk[16] = *(const float2*)&y[16];
                } else {
                    *(float2*)&chunk[18] = *(const float2*)&y[0];
                    *(float4*)&chunk[20] = *(const float4*)&y[2];
                    *(float4*)&chunk[24] = *(const float4*)&y[6];
                    *(float4*)&chunk[28] = *(const float4*)&y[10];
                    *(float4*)&chunk[32] = *(const float4*)&y[14];
                }
            }

            __syncthreads();  // all y written before async store reads smem
            if (t == 0) {
                asm volatile("fence.proxy.async.shared::cta;" ::: "memory");
                asm volatile(
                    "cp.async.bulk.global.shared::cta.bulk_group [%0], [%1], %2;"
                    :: "l"(og), "r"(s_bf[b]), "r"((uint32_t)BYTES_PER_TILE)
                    : "memory");
                asm volatile("cp.async.bulk.commit_group;" ::: "memory");
            }
            // no wait: store drains while we move on
        } else {
            // ---- partial tile: synchronous fallback path ----
            if (t == 0) {
                asm volatile("cp.async.bulk.wait_group.read 0;" ::: "memory");
            }
            __syncthreads();
#pragma unroll
            for (int k = 0; k < (WORDS_PER_TILE + TPB * 4 - 1) / (TPB * 4); k++) {
                int fi = (k * TPB + t) * 4;
                if (fi + 4 <= cnt) {
                    *(float4*)&buf[fi] = *(const float4*)&xg[fi];
                } else if (fi < cnt) {
                    for (int u = fi; u < cnt; u++) buf[u] = xg[u];
                }
            }
            __syncthreads();
            int lr0 = t * RPT;
            for (int lr = lr0; lr < lr0 + RPT && lr < rows_here; lr++) {
                float xp[9];
#pragma unroll
                for (int c = 0; c < 9; c++) xp[c] = buf[lr * 9 + c];
#pragma unroll
                for (int o = 0; o < 9; o++) {
                    float acc = ar[o * 10 + 9];
#pragma unroll
                    for (int c = 0; c < 9; c++)
                        acc = fmaf(ar[o * 10 + c], xp[c], acc);
                    buf[lr * 9 + o] = acc;
                }
            }
            __syncthreads();
#pragma unroll
            for (int k = 0; k < (WORDS_PER_TILE + TPB * 4 - 1) / (TPB * 4); k++) {
                int fi = (k * TPB + t) * 4;
                if (fi + 4 <= cnt) {
                    *(float4*)&og[fi] = *(const float4*)&buf[fi];
                } else if (fi < cnt) {
                    for (int u = fi; u < cnt; u++) og[u] = buf[u];
                }
            }
        }

        b = bn;
    }

    // drain the last async stores before exit
    if (t == 0) {
        asm volatile("cp.async.bulk.wait_group 0;" ::: "memory");
    }
}

extern "C" void kernel_launch(void* const* d_in, const int* in_sizes, int n_in,
                              void* d_out, int out_size) {
    const float* x = (const float*)d_in[0];  // [N*9]
    const float* w = (const float*)d_in[1];  // [8*9]
    const float* b = (const float*)d_in[2];  // [8]
    float* out = (float*)d_out;              // [N*9]

    int nrows = in_sizes[0] / 9;

    int ntiles = (nrows + ROWS_PER_TILE - 1) / ROWS_PER_TILE;
    int blocks = 148 * 7;
    if (blocks > ntiles) blocks = ntiles;
    affine_kernel<<<blocks, TPB>>>(x, w, b, out, nrows);
}